// round 9
// baseline (speedup 1.0000x reference)
#include <cuda_runtime.h>
#include <cstdint>

#define T_STEPS 800
#define UNITS   1024
#define BATCH   32
#define NFEAT   161
#define GRID    128
#define TPB     256     // xw/init kernels
#define TPR     128     // rnn kernel
#define CLIPV   20.0f

// 128 CTAs = 16 k-chunks x 8 col-tiles
#define CK 16
#define CN 8
#define KC 64            // UNITS / CK
#define NC 128           // UNITS / CN

#define SMEM_U_BYTES (KC * NC * 4)        // 32768: U tile
#define SMEM_H_BYTES (2 * KC * BATCH * 4) // 16384: h chunk, both dirs
#define SMEM_BYTES   (SMEM_U_BYTES + SMEM_H_BYTES)

#define QNAN_U 0x7fc00000u

__device__ float g_xw[T_STEPS * UNITS * BATCH];        // [t][u][b]
__device__ float g_part[3][2][CK][UNITS][BATCH];       // partials, NaN-sentinel
__device__ float g_hrep[3][CK][CN][2][KC][BATCH];      // per-consumer h replicas

typedef unsigned long long ull;

__device__ __forceinline__ void fma2(ull& d, ull a, ull b) {
    asm("fma.rn.f32x2 %0, %1, %2, %0;" : "+l"(d) : "l"(a), "l"(b));
}
__device__ __forceinline__ ull pack2(float v) {
    ull r; asm("mov.b64 %0, {%1, %1};" : "=l"(r) : "f"(v)); return r;
}
__device__ __forceinline__ float2 unpack2(ull v) {
    float2 r; asm("mov.b64 {%0, %1}, %2;" : "=f"(r.x), "=f"(r.y) : "l"(v)); return r;
}

// Volatile-ish L2 load for polling (re-executes every call; bypasses L1).
__device__ __forceinline__ float4 ld_poll(const float4* p) {
    float4 v;
    asm volatile("ld.global.cg.v4.f32 {%0,%1,%2,%3}, [%4];"
                 : "=f"(v.x), "=f"(v.y), "=f"(v.z), "=f"(v.w)
                 : "l"(p) : "memory");
    return v;
}
// NaN check robust to fast-math: integer compare (sentinel = qNaN).
// Real payloads are always finite (h clipped to [0,20], weights small).
__device__ __forceinline__ bool nan4(float4 v) {
    unsigned a = (__float_as_uint(v.x) & 0x7fffffffu) > 0x7f800000u;
    unsigned b = (__float_as_uint(v.y) & 0x7fffffffu) > 0x7f800000u;
    unsigned c = (__float_as_uint(v.z) & 0x7fffffffu) > 0x7f800000u;
    unsigned d = (__float_as_uint(v.w) & 0x7fffffffu) > 0x7f800000u;
    return (a | b | c | d) != 0u;
}
__device__ __forceinline__ void fence_argp() {
    asm volatile("fence.acq_rel.gpu;" ::: "memory");
}

// ---------------------------------------------------------------------------
// init: NaN-fill both exchange arenas (every harness call; globals persist)
// ---------------------------------------------------------------------------
#define N_PART_F (3 * 2 * CK * UNITS * BATCH)
#define N_HREP_F (3 * CK * CN * 2 * KC * BATCH)
__global__ void init_kernel() {
    const float qn = __uint_as_float(QNAN_U);
    int stride = gridDim.x * blockDim.x;
    for (int i = blockIdx.x * blockDim.x + threadIdx.x; i < N_PART_F; i += stride)
        ((float*)g_part)[i] = qn;
    for (int i = blockIdx.x * blockDim.x + threadIdx.x; i < N_HREP_F; i += stride)
        ((float*)g_hrep)[i] = qn;
}

// ---------------------------------------------------------------------------
// xw[t][u][b] = sum_f inputs[b][t][f] * W[f][u] + bias[u]
// ---------------------------------------------------------------------------
__global__ void __launch_bounds__(TPB) xw_kernel(const float* __restrict__ inp,
                                                 const float* __restrict__ W,
                                                 const float* __restrict__ bias) {
    __shared__ __align__(16) float in_s[NFEAT * 36];
    const int t   = blockIdx.y;
    const int u0  = blockIdx.x * 128;
    const int tid = threadIdx.x;
    const int bq  = tid & 7;
    const int cq  = tid >> 3;

    for (int idx = tid; idx < BATCH * NFEAT; idx += TPB) {
        int b = idx / NFEAT;
        int f = idx - b * NFEAT;
        in_s[f * 36 + b] = inp[(b * T_STEPS + t) * NFEAT + f];
    }
    __syncthreads();

    ull acc[4][2];
    #pragma unroll
    for (int i = 0; i < 4; i++) { acc[i][0] = 0ull; acc[i][1] = 0ull; }

    const float4* Wp = reinterpret_cast<const float4*>(W) + (u0 >> 2) + cq;
    #pragma unroll 1
    for (int f = 0; f < NFEAT; f++) {
        ulonglong2 ip = *reinterpret_cast<const ulonglong2*>(&in_s[f * 36 + bq * 4]);
        float4 w4 = __ldg(Wp + f * (UNITS / 4));
        ull w0 = pack2(w4.x), w1 = pack2(w4.y), w2 = pack2(w4.z), w3 = pack2(w4.w);
        fma2(acc[0][0], ip.x, w0); fma2(acc[0][1], ip.y, w0);
        fma2(acc[1][0], ip.x, w1); fma2(acc[1][1], ip.y, w1);
        fma2(acc[2][0], ip.x, w2); fma2(acc[2][1], ip.y, w2);
        fma2(acc[3][0], ip.x, w3); fma2(acc[3][1], ip.y, w3);
    }
    #pragma unroll
    for (int i = 0; i < 4; i++) {
        int u = u0 + cq * 4 + i;
        float bu = __ldg(bias + u);
        float2 a0 = unpack2(acc[i][0]);
        float2 a1 = unpack2(acc[i][1]);
        float4 v = make_float4(a0.x + bu, a0.y + bu, a1.x + bu, a1.y + bu);
        *reinterpret_cast<float4*>(&g_xw[(t * UNITS + u) * BATCH + bq * 4]) = v;
    }
}

// ---------------------------------------------------------------------------
// Persistent bidirectional scan — counter-free NaN-sentinel dataflow.
// CTA (kc,nc): produces partials (h-chunk kc x col-tile nc, both dirs),
// reduces slice = units [64kc+8nc, +8) x 2 dirs, publishes to 8 private
// replicas, and stages its chunk by polling its own replica.
// ---------------------------------------------------------------------------
__global__ void __launch_bounds__(TPR, 1) rnn_kernel(const float* __restrict__ Uw,
                                                     float* __restrict__ out) {
    extern __shared__ __align__(16) char smem_raw[];
    float* U_s = reinterpret_cast<float*>(smem_raw);                  // [64][128]
    float* h_s = reinterpret_cast<float*>(smem_raw + SMEM_U_BYTES);   // [2][64][32]

    const int tid = threadIdx.x;
    const int bid = blockIdx.x;
    const int kc  = bid >> 3;
    const int nc  = bid & 7;
    const int k0  = kc * KC;
    const int c0  = nc * NC;

    const int b0 = (tid & 7) * 4;        // 8 batch groups of 4
    const int cc = (tid >> 3) * 8;       // 16 col groups of 8

    // reduce identity: (dir, local unit in slice, batch-quad)
    const int rdir = tid >> 6;
    const int lu   = (tid >> 3) & 7;
    const int ru   = k0 + nc * 8 + lu;   // global unit
    const int rb4  = tid & 7;

    const float4 qn4 = make_float4(__uint_as_float(QNAN_U), __uint_as_float(QNAN_U),
                                   __uint_as_float(QNAN_U), __uint_as_float(QNAN_U));

    // ---- load U tile once (32 KB) ----
    for (int idx = tid; idx < KC * NC / 4; idx += TPR) {
        reinterpret_cast<float4*>(U_s)[idx] =
            __ldg(reinterpret_cast<const float4*>(Uw + k0 * UNITS + c0
                      + (idx >> 5) * UNITS) + (idx & 31));
    }
    // ---- h_{-1} = 0 ----
    for (int idx = tid; idx < 2 * KC * BATCH; idx += TPR) h_s[idx] = 0.0f;
    __syncthreads();

    int pb = 0;                          // buffer index = t % 3
    float4 hn;                           // this thread's reduced slice piece

    for (int t = 0; t < T_STEPS; t++) {
        // ---- fused GEMM (both dirs), acc[dir][bpair][col] ----
        ull acc[2][2][8];
        #pragma unroll
        for (int d = 0; d < 2; d++)
            #pragma unroll
            for (int p = 0; p < 2; p++)
                #pragma unroll
                for (int i = 0; i < 8; i++) acc[d][p][i] = 0ull;
        {
            const float* hp = h_s + b0;
            const float* up = U_s + cc;
            #pragma unroll 8
            for (int k = 0; k < KC; k++) {
                ulonglong2 hA = *reinterpret_cast<const ulonglong2*>(hp + k * BATCH);
                ulonglong2 hB = *reinterpret_cast<const ulonglong2*>(hp + KC * BATCH + k * BATCH);
                float4 uA = *reinterpret_cast<const float4*>(up + k * NC);
                float4 uB = *reinterpret_cast<const float4*>(up + k * NC + 4);
                ull s0 = pack2(uA.x), s1 = pack2(uA.y), s2 = pack2(uA.z), s3 = pack2(uA.w);
                ull s4 = pack2(uB.x), s5 = pack2(uB.y), s6 = pack2(uB.z), s7 = pack2(uB.w);
                fma2(acc[0][0][0], hA.x, s0); fma2(acc[0][1][0], hA.y, s0);
                fma2(acc[0][0][1], hA.x, s1); fma2(acc[0][1][1], hA.y, s1);
                fma2(acc[0][0][2], hA.x, s2); fma2(acc[0][1][2], hA.y, s2);
                fma2(acc[0][0][3], hA.x, s3); fma2(acc[0][1][3], hA.y, s3);
                fma2(acc[0][0][4], hA.x, s4); fma2(acc[0][1][4], hA.y, s4);
                fma2(acc[0][0][5], hA.x, s5); fma2(acc[0][1][5], hA.y, s5);
                fma2(acc[0][0][6], hA.x, s6); fma2(acc[0][1][6], hA.y, s6);
                fma2(acc[0][0][7], hA.x, s7); fma2(acc[0][1][7], hA.y, s7);
                fma2(acc[1][0][0], hB.x, s0); fma2(acc[1][1][0], hB.y, s0);
                fma2(acc[1][0][1], hB.x, s1); fma2(acc[1][1][1], hB.y, s1);
                fma2(acc[1][0][2], hB.x, s2); fma2(acc[1][1][2], hB.y, s2);
                fma2(acc[1][0][3], hB.x, s3); fma2(acc[1][1][3], hB.y, s3);
                fma2(acc[1][0][4], hB.x, s4); fma2(acc[1][1][4], hB.y, s4);
                fma2(acc[1][0][5], hB.x, s5); fma2(acc[1][1][5], hB.y, s5);
                fma2(acc[1][0][6], hB.x, s6); fma2(acc[1][1][6], hB.y, s6);
                fma2(acc[1][0][7], hB.x, s7); fma2(acc[1][1][7], hB.y, s7);
            }
        }

        // ---- publish partials (plain stcg; the values are the ready flags) ----
        #pragma unroll
        for (int d = 0; d < 2; d++)
            #pragma unroll
            for (int i = 0; i < 8; i++) {
                float2 a0 = unpack2(acc[d][0][i]);
                float2 a1 = unpack2(acc[d][1][i]);
                __stcg(reinterpret_cast<float4*>(
                           &g_part[pb][d][kc][c0 + cc + i][b0]),
                       make_float4(a0.x, a0.y, a1.x, a1.y));
            }

        // ---- prefetch x for the reduce ----
        int xt = rdir ? (T_STEPS - 1 - t) : t;
        float4 xv = __ldcg(reinterpret_cast<const float4*>(
                        g_xw + (xt * UNITS + ru) * BATCH) + rb4);

        // all GEMM reads of h_s done before staging overwrites it later
        __syncthreads();

        // ---- poll the 16 partials of our slice ----
        float4* pslot[CK];
        float4  pv[CK];
        #pragma unroll
        for (int j = 0; j < CK; j++) {
            pslot[j] = reinterpret_cast<float4*>(&g_part[pb][rdir][j][ru][0]) + rb4;
            pv[j] = ld_poll(pslot[j]);
        }
        for (;;) {
            unsigned bad = 0;
            #pragma unroll
            for (int j = 0; j < CK; j++)
                if (nan4(pv[j])) { bad = 1; pv[j] = ld_poll(pslot[j]); }
            if (!bad) break;
        }
        // reset slots to NaN for round t+3
        #pragma unroll
        for (int j = 0; j < CK; j++) __stcg(pslot[j], qn4);
        fence_argp();   // acquire(polls) + release(resets before replica stores)

        // ---- reduce + x + relu + clip ----
        {
            float4 s = xv;
            #pragma unroll
            for (int j = 0; j < CK; j++) {
                s.x += pv[j].x; s.y += pv[j].y; s.z += pv[j].z; s.w += pv[j].w;
            }
            hn.x = fminf(fmaxf(s.x, 0.f), CLIPV);
            hn.y = fminf(fmaxf(s.y, 0.f), CLIPV);
            hn.z = fminf(fmaxf(s.z, 0.f), CLIPV);
            hn.w = fminf(fmaxf(s.w, 0.f), CLIPV);
        }
        // ---- publish slice to all 8 consumers' private replicas ----
        #pragma unroll
        for (int c = 0; c < CN; c++)
            __stcg(reinterpret_cast<float4*>(
                       &g_hrep[pb][kc][c][rdir][nc * 8 + lu][0]) + rb4, hn);

        // ---- stage h_t from own replica (poll = stage), except last round ----
        if (t < T_STEPS - 1) {
            float4* hbase = reinterpret_cast<float4*>(&g_hrep[pb][kc][nc][0][0][0]);
            float4* hslot[8];
            float4  hv[8];
            #pragma unroll
            for (int i = 0; i < 8; i++) {
                hslot[i] = hbase + tid * 8 + i;
                hv[i] = ld_poll(hslot[i]);
            }
            for (;;) {
                unsigned bad = 0;
                #pragma unroll
                for (int i = 0; i < 8; i++)
                    if (nan4(hv[i])) { bad = 1; hv[i] = ld_poll(hslot[i]); }
                if (!bad) break;
            }
            #pragma unroll
            for (int i = 0; i < 8; i++)
                reinterpret_cast<float4*>(h_s)[tid * 8 + i] = hv[i];
            // reset replica for round t+3
            #pragma unroll
            for (int i = 0; i < 8; i++) __stcg(hslot[i], qn4);
            fence_argp();   // acquire(h polls) + release(resets before partials t+1)
            __syncthreads();
        }

        pb = pb + 1; if (pb == 3) pb = 0;
    }

    // ---- epilogue: combine dirs of the final slice, write out ----
    __syncthreads();                       // U_s free; reuse as scratch
    float4* fin = reinterpret_cast<float4*>(U_s);
    fin[tid] = hn;                         // [rdir*64 + lu*8 + rb4]
    __syncthreads();
    if (rdir == 0) {
        float4 f0 = fin[tid];
        float4 f1 = fin[64 + tid];
        float4 s = make_float4(f0.x + f1.x, f0.y + f1.y, f0.z + f1.z, f0.w + f1.w);
        int b = rb4 * 4;
        out[(b + 0) * UNITS + ru] = s.x;
        out[(b + 1) * UNITS + ru] = s.y;
        out[(b + 2) * UNITS + ru] = s.z;
        out[(b + 3) * UNITS + ru] = s.w;
    }
}

// ---------------------------------------------------------------------------
extern "C" void kernel_launch(void* const* d_in, const int* in_sizes, int n_in,
                              void* d_out, int out_size) {
    const float* inp  = (const float*)d_in[0];  // [32, 800, 161]
    const float* W    = (const float*)d_in[1];  // [161, 1024]
    const float* Uw   = (const float*)d_in[2];  // [1024, 1024]
    const float* bias = (const float*)d_in[3];  // [1024]
    float* out        = (float*)d_out;          // [32, 1024]

    cudaFuncSetAttribute(rnn_kernel, cudaFuncAttributeMaxDynamicSharedMemorySize,
                         SMEM_BYTES);

    init_kernel<<<1024, TPB>>>();
    xw_kernel<<<dim3(8, T_STEPS, 1), TPB>>>(inp, W, bias);
    rnn_kernel<<<GRID, TPR, SMEM_BYTES>>>(Uw, out);
}

// round 15
// speedup vs baseline: 1.5080x; 1.5080x over previous
#include <cuda_runtime.h>
#include <cuda_bf16.h>
#include <cstdint>

#define T_STEPS 800
#define UNITS   1024
#define BATCH   32
#define NFEAT   161
#define GRID    128
#define TPB     256
#define TPR     128
#define CLIPV   20.0f

#define CK 16
#define CN 8
#define KC 64
#define NC 128

// SMEM layout: bf16 tiles with 72-element (144B) pitch -> ldmatrix conflict-free
#define PITCHB   144
#define OFF_U1   0                      // U hi: 128 rows x 144B = 18432
#define OFF_U2   18432                  // U lo
#define OFF_H1   36864                  // h hi: 64 rows x 144B = 9216
#define OFF_H2   46080                  // h lo
#define OFF_SCR  55296                  // epilogue scratch [64][8] floats = 2KB
#define SMEM_BYTES 57360

__device__ float    g_xw[T_STEPS][BATCH][UNITS];
__device__ float    g_part[3][CK][64][UNITS];   // [buf][kchunk][n=dir*32+b][col]
__device__ float    g_h[3][64][UNITS];          // [buf][n][u]
__device__ unsigned g_P[CN];
__device__ unsigned g_C[CK];

typedef unsigned long long ull;

__device__ __forceinline__ void fma2(ull& d, ull a, ull b) {
    asm("fma.rn.f32x2 %0, %1, %2, %0;" : "+l"(d) : "l"(a), "l"(b));
}
__device__ __forceinline__ ull pack2(float v) {
    ull r; asm("mov.b64 %0, {%1, %1};" : "=l"(r) : "f"(v)); return r;
}
__device__ __forceinline__ float2 unpack2(ull v) {
    float2 r; asm("mov.b64 {%0, %1}, %2;" : "=f"(r.x), "=f"(r.y) : "l"(v)); return r;
}
__device__ __forceinline__ void ctr_arrive(unsigned* c) {
    __syncthreads();
    if (threadIdx.x == 0)
        asm volatile("red.release.gpu.global.add.u32 [%0], %1;"
                     :: "l"(c), "r"(1u) : "memory");
}
__device__ __forceinline__ void ctr_wait(unsigned* c, unsigned target) {
    if (threadIdx.x == 0) {
        unsigned v;
        do {
            asm volatile("ld.acquire.gpu.global.u32 %0, [%1];"
                         : "=r"(v) : "l"(c) : "memory");
        } while (v < target);
    }
    __syncthreads();
}
__device__ __forceinline__ uint32_t smem_u32(const void* p) {
    uint32_t a;
    asm("{ .reg .u64 t; cvta.to.shared.u64 t, %1; cvt.u32.u64 %0, t; }" : "=r"(a) : "l"(p));
    return a;
}
__device__ __forceinline__ uint32_t cvtpack(float hi, float lo) {
    uint32_t w;
    asm("cvt.rn.satfinite.bf16x2.f32 %0, %1, %2;" : "=r"(w) : "f"(hi), "f"(lo));
    return w;
}
__device__ __forceinline__ float bflo(uint32_t w) { return __uint_as_float(w << 16); }
__device__ __forceinline__ float bfhi(uint32_t w) { return __uint_as_float(w & 0xffff0000u); }
__device__ __forceinline__ float4 ldcg4(const float* p) {
    return __ldcg(reinterpret_cast<const float4*>(p));
}
__device__ __forceinline__ void ldsm4(uint32_t* r, uint32_t addr) {
    asm volatile("ldmatrix.sync.aligned.m8n8.x4.shared.b16 {%0,%1,%2,%3}, [%4];"
                 : "=r"(r[0]), "=r"(r[1]), "=r"(r[2]), "=r"(r[3]) : "r"(addr));
}
__device__ __forceinline__ void mma16816(float* d, const uint32_t* a, const uint32_t* b) {
    asm volatile("mma.sync.aligned.m16n8k16.row.col.f32.bf16.bf16.f32 "
                 "{%0,%1,%2,%3}, {%4,%5,%6,%7}, {%8,%9}, {%0,%1,%2,%3};"
                 : "+f"(d[0]), "+f"(d[1]), "+f"(d[2]), "+f"(d[3])
                 : "r"(a[0]), "r"(a[1]), "r"(a[2]), "r"(a[3]), "r"(b[0]), "r"(b[1]));
}

// ---------------------------------------------------------------------------
__global__ void init_kernel() {
    int i = blockIdx.x * blockDim.x + threadIdx.x;
    int stride = gridDim.x * blockDim.x;
    for (int j = i; j < 64 * UNITS; j += stride) ((float*)g_h)[j] = 0.0f;  // buf 0
    if (i < CN) g_P[i] = 0u;
    if (i < CK) g_C[i] = 0u;
}

// ---------------------------------------------------------------------------
// xw[t][b][u] = sum_f inp[b][t][f] * W[f][u] + bias[u]   (u-contiguous)
// ---------------------------------------------------------------------------
__global__ void __launch_bounds__(TPB) xw_kernel(const float* __restrict__ inp,
                                                 const float* __restrict__ W,
                                                 const float* __restrict__ bias) {
    __shared__ __align__(16) float in_s[NFEAT * 36];
    const int t = blockIdx.y, u0 = blockIdx.x * 128, tid = threadIdx.x;
    const int cq = tid & 31, bq = tid >> 5;
    const int uu = u0 + cq * 4, b0 = bq * 4;

    for (int idx = tid; idx < BATCH * NFEAT; idx += TPB) {
        int b = idx / NFEAT, f = idx - b * NFEAT;
        in_s[f * 36 + b] = inp[(b * T_STEPS + t) * NFEAT + f];
    }
    __syncthreads();

    ull acc[4][2];
    #pragma unroll
    for (int i = 0; i < 4; i++) { acc[i][0] = 0ull; acc[i][1] = 0ull; }

    const float4* Wp = reinterpret_cast<const float4*>(W) + (uu >> 2);
    #pragma unroll 1
    for (int f = 0; f < NFEAT; f++) {
        ulonglong2 ip = *reinterpret_cast<const ulonglong2*>(&in_s[f * 36 + b0]);
        float4 w4 = __ldg(Wp + f * (UNITS / 4));
        ull s0 = pack2(w4.x), s1 = pack2(w4.y), s2 = pack2(w4.z), s3 = pack2(w4.w);
        fma2(acc[0][0], ip.x, s0); fma2(acc[0][1], ip.y, s0);
        fma2(acc[1][0], ip.x, s1); fma2(acc[1][1], ip.y, s1);
        fma2(acc[2][0], ip.x, s2); fma2(acc[2][1], ip.y, s2);
        fma2(acc[3][0], ip.x, s3); fma2(acc[3][1], ip.y, s3);
    }
    float4 bv = *reinterpret_cast<const float4*>(bias + uu);
    float2 a0[4], a1[4];
    #pragma unroll
    for (int i = 0; i < 4; i++) { a0[i] = unpack2(acc[i][0]); a1[i] = unpack2(acc[i][1]); }
    *reinterpret_cast<float4*>(&g_xw[t][b0 + 0][uu]) =
        make_float4(a0[0].x + bv.x, a0[1].x + bv.y, a0[2].x + bv.z, a0[3].x + bv.w);
    *reinterpret_cast<float4*>(&g_xw[t][b0 + 1][uu]) =
        make_float4(a0[0].y + bv.x, a0[1].y + bv.y, a0[2].y + bv.z, a0[3].y + bv.w);
    *reinterpret_cast<float4*>(&g_xw[t][b0 + 2][uu]) =
        make_float4(a1[0].x + bv.x, a1[1].x + bv.y, a1[2].x + bv.z, a1[3].x + bv.w);
    *reinterpret_cast<float4*>(&g_xw[t][b0 + 3][uu]) =
        make_float4(a1[0].y + bv.x, a1[1].y + bv.y, a1[2].y + bv.z, a1[3].y + bv.w);
}

// ---------------------------------------------------------------------------
// Persistent scan: HMMA split-bf16 GEMM per CTA, P/C counter skeleton.
// D[n=dir*32+b][col] = h[n][:] . U[:, col]   (K = 64 per CTA)
// ---------------------------------------------------------------------------
__global__ void __launch_bounds__(TPR, 1) rnn_kernel(const float* __restrict__ Uw,
                                                     float* __restrict__ out) {
    extern __shared__ __align__(16) char sm[];
    const uint32_t sb = smem_u32(sm);
    float* scr = reinterpret_cast<float*>(sm + OFF_SCR);

    const int tid = threadIdx.x, wid = tid >> 5, lane = tid & 31;
    const int bid = blockIdx.x;
    const int kc = bid >> 3, nc = bid & 7;
    const int k0g = kc * KC, c0 = nc * NC;

    // staging / reduce identity
    const int n = tid >> 1, half = tid & 1;
    const int rdir = n >> 5, rb = n & 31;
    const int u4 = k0g + nc * 8 + half * 4;

    // ldmatrix per-lane address components (q = lane/8, rr = lane%8)
    const int q = lane >> 3, rr = lane & 7;
    // A (h) tile: matrices {rows+0..7,k0 | rows+8..15,k0 | rows+0..7,k0+8 | +8,+8}
    const uint32_t aoff = (uint32_t)((((q & 1) * 8 + rr) * PITCHB) + (q >> 1) * 16);
    // B (U) pair: matrices {cols+0..7,k0 | cols+0..7,k0+8 | cols+8..15,k0 | +8,+8}
    const int c_base = wid * 32;
    const uint32_t boff = (uint32_t)(((c_base + (q >> 1) * 8 + rr) * PITCHB) + (q & 1) * 16);

    // ---- build U tiles once: U1/U2[col][k] bf16, pitch 72 ----
    for (int idx = tid; idx < NC * KC; idx += TPR) {
        int m = idx & 127, k = idx >> 7;
        float u = __ldg(Uw + (k0g + k) * UNITS + c0 + m);
        __nv_bfloat16 u1 = __float2bfloat16(u);
        __nv_bfloat16 u2 = __float2bfloat16(u - __bfloat162float(u1));
        *reinterpret_cast<__nv_bfloat16*>(sm + OFF_U1 + m * PITCHB + k * 2) = u1;
        *reinterpret_cast<__nv_bfloat16*>(sm + OFF_U2 + m * PITCHB + k * 2) = u2;
    }
    __syncthreads();

    float4 hn;

    #pragma unroll 1
    for (int t = 0; t < T_STEPS; t++) {
        const int pb = t % 3, hb = (t + 1) % 3;

        // ---- wait h_{t-1} ready, stage + split into H1/H2 ----
        ctr_wait(&g_C[kc], 8u * (unsigned)t);
        {
            const float* hsrc = &g_h[pb][n][k0g + half * 32];
            uint32_t sbyte = (uint32_t)(n * PITCHB + half * 64);
            #pragma unroll
            for (int j = 0; j < 4; j++) {
                float4 a = ldcg4(hsrc + j * 8);
                float4 b4 = ldcg4(hsrc + j * 8 + 4);
                uint32_t w0 = cvtpack(a.y, a.x),   w1 = cvtpack(a.w, a.z);
                uint32_t w2 = cvtpack(b4.y, b4.x), w3 = cvtpack(b4.w, b4.z);
                asm volatile("st.shared.v4.b32 [%0], {%1,%2,%3,%4};"
                             :: "r"(sb + OFF_H1 + sbyte + j * 16),
                                "r"(w0), "r"(w1), "r"(w2), "r"(w3) : "memory");
                uint32_t v0 = cvtpack(a.y - bfhi(w0),   a.x - bflo(w0));
                uint32_t v1 = cvtpack(a.w - bfhi(w1),   a.z - bflo(w1));
                uint32_t v2 = cvtpack(b4.y - bfhi(w2),  b4.x - bflo(w2));
                uint32_t v3 = cvtpack(b4.w - bfhi(w3),  b4.z - bflo(w3));
                asm volatile("st.shared.v4.b32 [%0], {%1,%2,%3,%4};"
                             :: "r"(sb + OFF_H2 + sbyte + j * 16),
                                "r"(v0), "r"(v1), "r"(v2), "r"(v3) : "memory");
            }
        }
        __syncthreads();

        // ---- GEMM: U1h1 + U1h2 + U2h1 via mma.sync ----
        float d[4][4][4];
        #pragma unroll
        for (int mt = 0; mt < 4; mt++)
            #pragma unroll
            for (int nt = 0; nt < 4; nt++)
                #pragma unroll
                for (int i = 0; i < 4; i++) d[mt][nt][i] = 0.0f;

        #pragma unroll
        for (int ks = 0; ks < 4; ks++) {
            const uint32_t kb = (uint32_t)(ks * 32);   // 16 elems = 32 bytes
            uint32_t ah1[4][4], ah2[4][4], bu1[2][4], bu2[2][4];
            #pragma unroll
            for (int mt = 0; mt < 4; mt++)
                ldsm4(ah1[mt], sb + OFF_H1 + aoff + mt * (16 * PITCHB) + kb);
            #pragma unroll
            for (int p = 0; p < 2; p++)
                ldsm4(bu1[p], sb + OFF_U1 + boff + p * (16 * PITCHB) + kb);
            #pragma unroll
            for (int mt = 0; mt < 4; mt++)
                #pragma unroll
                for (int nt = 0; nt < 4; nt++)
                    mma16816(d[mt][nt], ah1[mt], &bu1[nt >> 1][(nt & 1) * 2]);
            #pragma unroll
            for (int p = 0; p < 2; p++)
                ldsm4(bu2[p], sb + OFF_U2 + boff + p * (16 * PITCHB) + kb);
            #pragma unroll
            for (int mt = 0; mt < 4; mt++)
                #pragma unroll
                for (int nt = 0; nt < 4; nt++)
                    mma16816(d[mt][nt], ah1[mt], &bu2[nt >> 1][(nt & 1) * 2]);
            #pragma unroll
            for (int mt = 0; mt < 4; mt++)
                ldsm4(ah2[mt], sb + OFF_H2 + aoff + mt * (16 * PITCHB) + kb);
            #pragma unroll
            for (int mt = 0; mt < 4; mt++)
                #pragma unroll
                for (int nt = 0; nt < 4; nt++)
                    mma16816(d[mt][nt], ah2[mt], &bu1[nt >> 1][(nt & 1) * 2]);
        }

        // ---- store partials: D rows = n, cols consecutive u -> st.v2 ----
        {
            float* gp = &g_part[pb][kc][0][0];
            const int urow = c0 + c_base + (lane & 3) * 2;
            const int nrow = lane >> 2;
            #pragma unroll
            for (int mt = 0; mt < 4; mt++)
                #pragma unroll
                for (int nt = 0; nt < 4; nt++) {
                    int u = urow + nt * 8;
                    int r0 = mt * 16 + nrow;
                    __stcg(reinterpret_cast<float2*>(gp + r0 * UNITS + u),
                           make_float2(d[mt][nt][0], d[mt][nt][1]));
                    __stcg(reinterpret_cast<float2*>(gp + (r0 + 8) * UNITS + u),
                           make_float2(d[mt][nt][2], d[mt][nt][3]));
                }
        }
        ctr_arrive(&g_P[nc]);

        // prefetch x for the reduce
        int xt = rdir ? (T_STEPS - 1 - t) : t;
        float4 xv = ldcg4(&g_xw[xt][rb][u4]);

        // ---- reduce own slice: thread (n, half) -> units u4..u4+3 ----
        ctr_wait(&g_P[kc >> 1], 16u * (unsigned)(t + 1));
        {
            float4 s = xv;
            #pragma unroll
            for (int j = 0; j < CK; j++) {
                float4 p = ldcg4(&g_part[pb][j][n][u4]);
                s.x += p.x; s.y += p.y; s.z += p.z; s.w += p.w;
            }
            hn.x = fminf(fmaxf(s.x, 0.f), CLIPV);
            hn.y = fminf(fmaxf(s.y, 0.f), CLIPV);
            hn.z = fminf(fmaxf(s.z, 0.f), CLIPV);
            hn.w = fminf(fmaxf(s.w, 0.f), CLIPV);
            *reinterpret_cast<float4*>(&g_h[hb][n][u4]) = hn;
        }
        ctr_arrive(&g_C[kc]);
    }

    // ---- epilogue: out[b][u] = hf + hb for this CTA's slice ----
    *reinterpret_cast<float4*>(&scr[n * 8 + half * 4]) = hn;
    __syncthreads();
    if (tid < 32) {
        int b = tid;
        float4 f0 = *reinterpret_cast<float4*>(&scr[b * 8]);
        float4 f1 = *reinterpret_cast<float4*>(&scr[(b + 32) * 8]);
        float4 g0 = *reinterpret_cast<float4*>(&scr[b * 8 + 4]);
        float4 g1 = *reinterpret_cast<float4*>(&scr[(b + 32) * 8 + 4]);
        int ub = k0g + nc * 8;
        *reinterpret_cast<float4*>(&out[b * UNITS + ub]) =
            make_float4(f0.x + f1.x, f0.y + f1.y, f0.z + f1.z, f0.w + f1.w);
        *reinterpret_cast<float4*>(&out[b * UNITS + ub + 4]) =
            make_float4(g0.x + g1.x, g0.y + g1.y, g0.z + g1.z, g0.w + g1.w);
    }
}

// ---------------------------------------------------------------------------
extern "C" void kernel_launch(void* const* d_in, const int* in_sizes, int n_in,
                              void* d_out, int out_size) {
    const float* inp  = (const float*)d_in[0];
    const float* W    = (const float*)d_in[1];
    const float* Uw   = (const float*)d_in[2];
    const float* bias = (const float*)d_in[3];
    float* out        = (float*)d_out;

    cudaFuncSetAttribute(rnn_kernel, cudaFuncAttributeMaxDynamicSharedMemorySize,
                         SMEM_BYTES);

    init_kernel<<<64, TPB>>>();
    xw_kernel<<<dim3(8, T_STEPS, 1), TPB>>>(inp, W, bias);
    rnn_kernel<<<GRID, TPR, SMEM_BYTES>>>(Uw, out);
}